// round 7
// baseline (speedup 1.0000x reference)
#include <cuda_runtime.h>

#define OH   113        // output windows per dim
#define P    24         // smem row pitch (in float2 elements)
#define NT   512        // threads per CTA

// Tile: 8x8 windows. Local pyramid extents (rows x cols):
//   L0: 23x23  L1: 22x22  L2: 20x20   (L3/L4 folded into epilogue)
// Pyramid entry: float2 { .x = max, .y = min }
#define R0   0
#define R1   (23*P)              // 552
#define R2   (R1 + 22*P)         // 1080
#define RT   (R2 + 20*P)         // 1560 float2 = 12.2KB

__global__ __launch_bounds__(NT)
void k_fused(const float* __restrict__ img, float* __restrict__ out) {
    __shared__ float2 s[RT];        // (max, min) pyramid
    __shared__ float  c0[23 * 9];   // L0 column range-sums (16 taps), pitch 9
    __shared__ float  c1[22 * 9];   // L1 column range-sums (8 taps, stride 2)

    const int tid = threadIdx.x;
    const int I0 = blockIdx.y * 8;      // tile origin, stride-4 grid units
    const int J0 = blockIdx.x * 8;

    // ---- Phase A: level-0 4x4 max/min over 23x23 local origins ----
    // Branchless clamp: clamped entries only feed discarded windows.
    const float4* p4 = (const float4*)img;
    for (int e = tid; e < 23 * 23; e += NT) {
        int i = e / 23, j = e - i * 23;
        int gi = min(I0 + i, 127), gj = min(J0 + j, 127);
        float mx = -3.4e38f, mn = 3.4e38f;
#pragma unroll
        for (int k = 0; k < 4; k++) {
            float4 v = p4[(4 * gi + k) * 128 + gj];
            mx = fmaxf(mx, fmaxf(fmaxf(v.x, v.y), fmaxf(v.z, v.w)));
            mn = fminf(mn, fminf(fminf(v.x, v.y), fminf(v.z, v.w)));
        }
        s[R0 + i * P + j] = make_float2(mx, mn);
    }
    __syncthreads();

    // ---- Phase B: L1 (22x22, 4 taps) and c0 (23x8, 16 taps) from L0 ----
    for (int e = tid; e < 22 * 22 + 23 * 8; e += NT) {
        if (e < 22 * 22) {
            int i = e / 22, j = e - i * 22;
            int b = R0 + i * P + j;
            float2 a0 = s[b],     a1 = s[b + 1];
            float2 a2 = s[b + P], a3 = s[b + P + 1];
            s[R1 + i * P + j] = make_float2(
                fmaxf(fmaxf(a0.x, a1.x), fmaxf(a2.x, a3.x)),
                fminf(fminf(a0.y, a1.y), fminf(a2.y, a3.y)));
        } else {
            int f = e - 22 * 22;
            int i = f >> 3, J = f & 7;
            float sum = 0.f;
#pragma unroll
            for (int q = 0; q < 16; q++) {
                float2 v = s[R0 + i * P + J + q];
                sum += v.x - v.y;
            }
            c0[i * 9 + J] = sum;
        }
    }
    __syncthreads();

    // ---- Phase C: L2 (20x20, 4 taps d=2) and c1 (22x8, 8 taps stride 2) ----
    for (int e = tid; e < 20 * 20 + 22 * 8; e += NT) {
        if (e < 20 * 20) {
            int i = e / 20, j = e - i * 20;
            int b = R1 + i * P + j;
            float2 a0 = s[b],         a1 = s[b + 2];
            float2 a2 = s[b + 2 * P], a3 = s[b + 2 * P + 2];
            s[R2 + i * P + j] = make_float2(
                fmaxf(fmaxf(a0.x, a1.x), fmaxf(a2.x, a3.x)),
                fminf(fminf(a0.y, a1.y), fminf(a2.y, a3.y)));
        } else {
            int f = e - 20 * 20;
            int i = f >> 3, J = f & 7;
            float sum = 0.f;
#pragma unroll
            for (int q = 0; q < 8; q++) {
                float2 v = s[R1 + i * P + J + 2 * q];
                sum += v.x - v.y;
            }
            c1[i * 9 + J] = sum;
        }
    }
    __syncthreads();

    // ---- Phase E: 8 threads per window (64 windows x 8 = 512) ----
    int w  = tid >> 3;          // window 0..63
    int h  = tid & 7;           // eighth index
    int ti = w >> 3, tj = w & 7;

    float s0 = 0.f, s1, s2 = 0.f;
    // s0: 16 c0 rows, 2 per thread (rows p = 2h+k)
#pragma unroll
    for (int k = 0; k < 2; k++)
        s0 += c0[(ti + 2 * h + k) * 9 + tj];
    // s1: 8 c1 rows (stride 2), 1 per thread (row p = h)
    s1 = c1[(ti + 2 * h) * 9 + tj];
    // s2 and s4 share taps: 16 L2 entries, 2 per thread:
    //   p = h>>1, q = 2*(h&1)+k
    float mx4 = -3.4e38f, mn4 = 3.4e38f;
#pragma unroll
    for (int k = 0; k < 2; k++) {
        float2 v = s[R2 + (ti + 4 * (h >> 1)) * P + tj + 4 * (2 * (h & 1) + k)];
        s2 += v.x - v.y;
        mx4 = fmaxf(mx4, v.x);
        mn4 = fminf(mn4, v.y);
    }
    // s3: 4 boxes of 32x32, each box split across 2 threads.
    //   box = h>>1 -> (bp,bq) = (h>>2, (h>>1)&1); half a = h&1 (2 taps: b=0,1)
    float bmx = -3.4e38f, bmn = 3.4e38f;
    {
        int bp = h >> 2, bq = (h >> 1) & 1, a = h & 1;
#pragma unroll
        for (int b = 0; b < 2; b++) {
            float2 v = s[R2 + (ti + 8 * bp + 4 * a) * P + tj + 8 * bq + 4 * b];
            bmx = fmaxf(bmx, v.x);
            bmn = fminf(bmn, v.y);
        }
    }

    // Combine box halves (lanes h, h^1)
    bmx = fmaxf(bmx, __shfl_xor_sync(0xFFFFFFFFu, bmx, 1));
    bmn = fminf(bmn, __shfl_xor_sync(0xFFFFFFFFu, bmn, 1));
    float s3 = bmx - bmn;       // full box range, duplicated in lane pair

    // Tree reductions within the 8-lane group
    s0 += __shfl_xor_sync(0xFFFFFFFFu, s0, 1);
    s1 += __shfl_xor_sync(0xFFFFFFFFu, s1, 1);
    s2 += __shfl_xor_sync(0xFFFFFFFFu, s2, 1);
    mx4 = fmaxf(mx4, __shfl_xor_sync(0xFFFFFFFFu, mx4, 1));
    mn4 = fminf(mn4, __shfl_xor_sync(0xFFFFFFFFu, mn4, 1));
#pragma unroll
    for (int off = 2; off <= 4; off <<= 1) {
        s0  += __shfl_xor_sync(0xFFFFFFFFu, s0, off);
        s1  += __shfl_xor_sync(0xFFFFFFFFu, s1, off);
        s2  += __shfl_xor_sync(0xFFFFFFFFu, s2, off);
        s3  += __shfl_xor_sync(0xFFFFFFFFu, s3, off);   // sums the 4 boxes
        mx4 = fmaxf(mx4, __shfl_xor_sync(0xFFFFFFFFu, mx4, off));
        mn4 = fminf(mn4, __shfl_xor_sync(0xFFFFFFFFu, mn4, off));
    }

    int I = I0 + ti, J = J0 + tj;
    if (h == 0 && I < OH && J < OH) {
        float s4 = mx4 - mn4;
        float num = 2.0f * __log2f(s0) + 3.0f * __log2f(s1)
                  + 4.0f * __log2f(s2) + 5.0f * __log2f(s3)
                  + 6.0f * __log2f(s4);
        out[I * OH + J] = -num * (1.0f / 90.0f);
    }
}

// ---------------------------------------------------------------------------
extern "C" void kernel_launch(void* const* d_in, const int* in_sizes, int n_in,
                              void* d_out, int out_size) {
    const float* img = (const float*)d_in[0];
    float* out = (float*)d_out;
    dim3 grid(15, 15);          // ceil(113/8) per dim = 225 CTAs
    k_fused<<<grid, NT>>>(img, out);
}